// round 11
// baseline (speedup 1.0000x reference)
#include <cuda_runtime.h>
#include <cstdint>

#define Bq 32
#define Hh 32
#define KVH 8
#define Gq 4
#define Dd 128
#define BS 128
#define NB 448
#define BPS 14                      /* blocks per sequence = NB/Bq */
#define SCALE 0.08838834764831845f
#define SVS  132                    /* Sv row stride: rows stay 16B-aligned */

// Flash-decode partial scratch (static device globals: allocation-free).
__device__ float g_po[(size_t)NB * KVH * Gq * Dd];   // ~7.3 MB
__device__ float g_pm[NB * KVH * Gq];
__device__ float g_pl[NB * KVH * Gq];
__device__ int   g_cnt[Bq * KVH];                    // zero-init, reset after merge

// Packed f32x2 FMA (FFMA2) — 2 MACs per issue slot; only reachable via PTX.
__device__ __forceinline__ float2 ffma2(float2 a, float2 b, float2 c) {
    unsigned long long ua = *reinterpret_cast<unsigned long long*>(&a);
    unsigned long long ub = *reinterpret_cast<unsigned long long*>(&b);
    unsigned long long uc = *reinterpret_cast<unsigned long long*>(&c);
    unsigned long long ur;
    asm("fma.rn.f32x2 %0, %1, %2, %3;" : "=l"(ur) : "l"(ua), "l"(ub), "l"(uc));
    return *reinterpret_cast<float2*>(&ur);
}

__device__ __forceinline__ void prefetch_l2(const void* p) {
    asm volatile("prefetch.global.L2 [%0];" :: "l"(p));
}

__global__ __launch_bounds__(128, 10)
void attn_fused_kernel(
    const float* __restrict__ query,
    const float* __restrict__ knew,
    const float* __restrict__ vnew,
    const float* __restrict__ kcache,
    const float* __restrict__ vcache,
    const int*   __restrict__ block_list,
    const int*   __restrict__ block_groups,
    const float* __restrict__ block_bias,
    const int*   __restrict__ block_indices,
    const int*   __restrict__ block_offsets,
    const float* __restrict__ alibi_blocks,
    const float* __restrict__ slopes,
    float*       __restrict__ out)
{
    __shared__ float Qs[Gq][Dd];        // 2 KB scaled Q
    __shared__ float Sv[Gq][SVS];       // 2.1 KB p values -> merge coefs
    __shared__ float Ored[4][Gq][Dd];   // 8 KB per-warp PV partials (merge scratch too)
    __shared__ float wmax[4][Gq];
    __shared__ float psum[4][Gq];
    __shared__ int   s_last, s_cnt;
    __shared__ short s_list[BPS + 2];

    // kvh-fast grid: 8 consecutive CTAs (same n, kvh 0..7) stream interleaved
    // 512B slices of the SAME contiguous 256 KB region -> near-sequential
    // aggregate DRAM request stream (burst/row-buffer friendly).
    const int kvh = blockIdx.x;
    const int n   = blockIdx.y;
    const int tid = threadIdx.x;
    const int w   = tid >> 5;
    const int ln  = tid & 31;

    const int b    = block_groups[n];
    const int cblk = block_list[n];

    // validity of own token (masked tail of last block has bias = -1e9)
    const float bb_t    = block_bias[n * BS + tid];
    const float ab_t    = alibi_blocks[n * BS + tid];
    const int   valid_t = bb_t > -1.0e8f;

    // decode-token insertion: warp-uniform ballot, race-free, no smem
    int ins_slot = -1, ins_b = 0;
    {
        const unsigned mask =
            __ballot_sync(0xffffffffu, block_indices[ln] == cblk);
        if (mask) {
            ins_b    = __ffs(mask) - 1;
            ins_slot = block_offsets[ins_b];
        }
    }

    const size_t rowbase = (((size_t)cblk * BS + tid) * KVH + kvh) * Dd;

    // stage pre-scaled Q (warp w -> head w)
    {
        const int dq = ln * 4;
        float4 q4 = *reinterpret_cast<const float4*>(
            query + (size_t)b * Hh * Dd + (size_t)(kvh * Gq + w) * Dd + dq);
        q4.x *= SCALE; q4.y *= SCALE; q4.z *= SCALE; q4.w *= SCALE;
        *reinterpret_cast<float4*>(&Qs[w][dq]) = q4;
    }
    const float sl0 = slopes[kvh * Gq + 0];
    const float sl1 = slopes[kvh * Gq + 1];
    const float sl2 = slopes[kvh * Gq + 2];
    const float sl3 = slopes[kvh * Gq + 3];

    const int nvalid = __syncthreads_count(valid_t);   // barrier + count

    // ---------------- QK: thread owns token tid, K streamed from global ----------------
    // 8 batches of 4 LDG.128 (16 staging regs) -> fits the 10-CTA register cap.
    float2 acc[Gq];
    #pragma unroll
    for (int h = 0; h < Gq; h++) acc[h] = make_float2(0.f, 0.f);

    if (valid_t) {
        const float* krow =
            (tid == ins_slot)
              ? (knew + ((size_t)ins_b * KVH + kvh) * Dd)
              : (kcache + rowbase);
        #pragma unroll
        for (int cb = 0; cb < 8; cb++) {
            float4 kb[4];                         // 4 LDG.128 in flight
            #pragma unroll
            for (int j = 0; j < 4; j++)
                kb[j] = *reinterpret_cast<const float4*>(krow + (cb * 4 + j) * 4);
            #pragma unroll
            for (int j = 0; j < 4; j++) {
                const int c4 = (cb * 4 + j) * 4;
                const float2 klo = make_float2(kb[j].x, kb[j].y);
                const float2 khi = make_float2(kb[j].z, kb[j].w);
                #pragma unroll
                for (int h = 0; h < Gq; h++) {
                    const float4 q4 = *reinterpret_cast<const float4*>(&Qs[h][c4]);
                    acc[h] = ffma2(klo, make_float2(q4.x, q4.y), acc[h]);
                    acc[h] = ffma2(khi, make_float2(q4.z, q4.w), acc[h]);
                }
            }
        }
    }

    // prefetch V tile into L2 NOW (short eviction window: only softmax between
    // here and PV use, so lines survive in L2 instead of being thrashed)
    if (valid_t) {
        const float* vr = vcache + rowbase;
        prefetch_l2(vr);       prefetch_l2(vr + 32);
        prefetch_l2(vr + 64);  prefetch_l2(vr + 96);
    }

    // ---------------- softmax (scores live in-register) ----------------
    float s0, s1, s2, s3;
    if (valid_t) {
        s0 = acc[0].x + acc[0].y + ab_t * sl0 + bb_t;
        s1 = acc[1].x + acc[1].y + ab_t * sl1 + bb_t;
        s2 = acc[2].x + acc[2].y + ab_t * sl2 + bb_t;
        s3 = acc[3].x + acc[3].y + ab_t * sl3 + bb_t;
    } else {
        s0 = s1 = s2 = s3 = -1.0e30f;
    }
    {
        float m0 = s0, m1 = s1, m2 = s2, m3 = s3;
        #pragma unroll
        for (int off = 16; off > 0; off >>= 1) {
            m0 = fmaxf(m0, __shfl_xor_sync(0xffffffffu, m0, off));
            m1 = fmaxf(m1, __shfl_xor_sync(0xffffffffu, m1, off));
            m2 = fmaxf(m2, __shfl_xor_sync(0xffffffffu, m2, off));
            m3 = fmaxf(m3, __shfl_xor_sync(0xffffffffu, m3, off));
        }
        if (ln == 0) { wmax[w][0] = m0; wmax[w][1] = m1; wmax[w][2] = m2; wmax[w][3] = m3; }
    }
    __syncthreads();
    const float m0 = fmaxf(fmaxf(wmax[0][0], wmax[1][0]), fmaxf(wmax[2][0], wmax[3][0]));
    const float m1 = fmaxf(fmaxf(wmax[0][1], wmax[1][1]), fmaxf(wmax[2][1], wmax[3][1]));
    const float m2 = fmaxf(fmaxf(wmax[0][2], wmax[1][2]), fmaxf(wmax[2][2], wmax[3][2]));
    const float m3 = fmaxf(fmaxf(wmax[0][3], wmax[1][3]), fmaxf(wmax[2][3], wmax[3][3]));

    const float p0 = valid_t ? __expf(s0 - m0) : 0.f;
    const float p1 = valid_t ? __expf(s1 - m1) : 0.f;
    const float p2 = valid_t ? __expf(s2 - m2) : 0.f;
    const float p3 = valid_t ? __expf(s3 - m3) : 0.f;
    Sv[0][tid] = p0; Sv[1][tid] = p1; Sv[2][tid] = p2; Sv[3][tid] = p3;
    {
        float t0 = p0, t1 = p1, t2 = p2, t3 = p3;
        #pragma unroll
        for (int off = 16; off > 0; off >>= 1) {
            t0 += __shfl_xor_sync(0xffffffffu, t0, off);
            t1 += __shfl_xor_sync(0xffffffffu, t1, off);
            t2 += __shfl_xor_sync(0xffffffffu, t2, off);
            t3 += __shfl_xor_sync(0xffffffffu, t3, off);
        }
        if (ln == 0) { psum[w][0] = t0; psum[w][1] = t1; psum[w][2] = t2; psum[w][3] = t3; }
    }
    __syncthreads();

    // ---------------- PV: warp w -> 32 tokens (pairs), lane owns 4 d's ----------------
    float2 olo[Gq], ohi[Gq];
    #pragma unroll
    for (int h = 0; h < Gq; h++) { olo[h] = make_float2(0.f, 0.f); ohi[h] = make_float2(0.f, 0.f); }
    const int d0 = ln * 4;

    if (w * 32 < nvalid) {
        const float* vbase = vcache + (((size_t)cblk * BS + w * 32) * KVH + kvh) * Dd + d0;
        #pragma unroll 4
        for (int i2 = 0; i2 < 16; i2++) {
            const int t0 = w * 32 + i2 * 2;
            float2 p2[Gq];                        // 8 live regs (vs 16 with float4)
            #pragma unroll
            for (int h = 0; h < Gq; h++)
                p2[h] = *reinterpret_cast<const float2*>(&Sv[h][t0]);
            #pragma unroll
            for (int j = 0; j < 2; j++) {
                if (t0 + j < nvalid) {
                    const float4 v4 = *reinterpret_cast<const float4*>(
                        vbase + (size_t)(i2 * 2 + j) * KVH * Dd);
                    const float2 vlo = make_float2(v4.x, v4.y);
                    const float2 vhi = make_float2(v4.z, v4.w);
                    #pragma unroll
                    for (int h = 0; h < Gq; h++) {
                        const float pb = (j == 0) ? p2[h].x : p2[h].y;
                        const float2 pp = make_float2(pb, pb);
                        olo[h] = ffma2(pp, vlo, olo[h]);
                        ohi[h] = ffma2(pp, vhi, ohi[h]);
                    }
                }
            }
        }
        // exact decode-token correction: o += p_ins * (v_new - v_cache_old)
        if (ins_slot >= (w * 32) && ins_slot < (w * 32 + 32)) {
            const float4 vo = *reinterpret_cast<const float4*>(
                vcache + (((size_t)cblk * BS + ins_slot) * KVH + kvh) * Dd + d0);
            const float4 vn = *reinterpret_cast<const float4*>(
                vnew + ((size_t)ins_b * KVH + kvh) * Dd + d0);
            const float2 dlo = make_float2(vn.x - vo.x, vn.y - vo.y);
            const float2 dhi = make_float2(vn.z - vo.z, vn.w - vo.w);
            #pragma unroll
            for (int h = 0; h < Gq; h++) {
                const float pb = Sv[h][ins_slot];
                const float2 pp = make_float2(pb, pb);
                olo[h] = ffma2(pp, dlo, olo[h]);
                ohi[h] = ffma2(pp, dhi, ohi[h]);
            }
        }
    }

    #pragma unroll
    for (int h = 0; h < Gq; h++)
        *reinterpret_cast<float4*>(&Ored[w][h][d0]) =
            make_float4(olo[h].x, olo[h].y, ohi[h].x, ohi[h].y);
    __syncthreads();

    // cross-warp sum + write partials (warp w -> head w, lane -> d chunk)
    {
        const float4 o0 = *reinterpret_cast<const float4*>(&Ored[0][w][d0]);
        const float4 o1 = *reinterpret_cast<const float4*>(&Ored[1][w][d0]);
        const float4 o2 = *reinterpret_cast<const float4*>(&Ored[2][w][d0]);
        const float4 o3 = *reinterpret_cast<const float4*>(&Ored[3][w][d0]);
        const float4 acc4 = make_float4(o0.x + o1.x + o2.x + o3.x,
                                        o0.y + o1.y + o2.y + o3.y,
                                        o0.z + o1.z + o2.z + o3.z,
                                        o0.w + o1.w + o2.w + o3.w);
        *reinterpret_cast<float4*>(
            &g_po[(((size_t)n * KVH + kvh) * Gq + w) * Dd + d0]) = acc4;
    }
    if (tid < Gq) {
        const size_t idx = ((size_t)n * KVH + kvh) * Gq + tid;
        g_pm[idx] = (tid == 0) ? m0 : (tid == 1) ? m1 : (tid == 2) ? m2 : m3;
        g_pl[idx] = psum[0][tid] + psum[1][tid] + psum[2][tid] + psum[3][tid];
    }

    // ---------------- fused merge: last CTA of (b, kvh) group ----------------
    __threadfence();
    __syncthreads();
    if (tid == 0)
        s_last = (atomicAdd(&g_cnt[b * KVH + kvh], 1) == (BPS - 1));
    __syncthreads();
    if (!s_last) return;

    // parallel flag fill (alias Ored as scratch), ordered compaction
    unsigned char* flag = reinterpret_cast<unsigned char*>(&Ored[0][0][0]);
    #pragma unroll
    for (int j = 0; j < (NB + 127) / 128; j++) {
        const int nn = tid + j * 128;
        if (nn < NB) flag[nn] = (block_groups[nn] == b) ? 1 : 0;
    }
    __syncthreads();
    if (tid == 0) {
        int c = 0;
        for (int nn = 0; nn < NB && c < BPS; nn++)
            if (flag[nn]) s_list[c++] = (short)nn;
        s_cnt = c;
    }
    __syncthreads();
    const int cnt = s_cnt;

    if (tid < Gq) {                    // rescale coefs (reuse Sv rows)
        const int h = tid;
        float M = -1.0e30f;
        for (int i = 0; i < cnt; i++)
            M = fmaxf(M, g_pm[((size_t)s_list[i] * KVH + kvh) * Gq + h]);
        float den = 0.f;
        for (int i = 0; i < cnt; i++) {
            const size_t idx = ((size_t)s_list[i] * KVH + kvh) * Gq + h;
            const float e = __expf(g_pm[idx] - M);
            Sv[h][i] = e;
            den += g_pl[idx] * e;
        }
        const float inv = 1.f / den;
        for (int i = 0; i < cnt; i++) Sv[h][i] *= inv;
    }
    __syncthreads();

    {
        float4 acc4 = make_float4(0.f, 0.f, 0.f, 0.f);
        for (int i = 0; i < cnt; i++) {
            const float c = Sv[w][i];
            const float4 ov = *reinterpret_cast<const float4*>(
                &g_po[(((size_t)s_list[i] * KVH + kvh) * Gq + w) * Dd + d0]);
            acc4.x += c * ov.x; acc4.y += c * ov.y;
            acc4.z += c * ov.z; acc4.w += c * ov.w;
        }
        *reinterpret_cast<float4*>(
            &out[(size_t)b * Hh * Dd + (size_t)(kvh * Gq + w) * Dd + d0]) = acc4;
    }
    if (tid == 0) g_cnt[b * KVH + kvh] = 0;   // reset for next replay
}

extern "C" void kernel_launch(void* const* d_in, const int* in_sizes, int n_in,
                              void* d_out, int out_size)
{
    const float* query         = (const float*)d_in[0];
    const float* key           = (const float*)d_in[1];
    const float* value         = (const float*)d_in[2];
    const float* key_cache     = (const float*)d_in[3];
    const float* value_cache   = (const float*)d_in[4];
    const int*   block_list    = (const int*)d_in[5];
    const int*   block_groups  = (const int*)d_in[6];
    /* d_in[7] block_mapping: one-hot, implied by block_groups */
    const float* block_bias    = (const float*)d_in[8];
    const int*   block_indices = (const int*)d_in[9];
    const int*   block_offsets = (const int*)d_in[10];
    const float* alibi_blocks  = (const float*)d_in[11];
    const float* alibi_slopes  = (const float*)d_in[12];

    attn_fused_kernel<<<dim3(KVH, NB), 128>>>(
        query, key, value, key_cache, value_cache,
        block_list, block_groups, block_bias,
        block_indices, block_offsets, alibi_blocks, alibi_slopes,
        (float*)d_out);
}

// round 12
// speedup vs baseline: 1.3396x; 1.3396x over previous
#include <cuda_runtime.h>
#include <cstdint>

#define Bq 32
#define Hh 32
#define KVH 8
#define Gq 4
#define Dd 128
#define BS 128
#define NB 448
#define BPS 14                      /* blocks per sequence = NB/Bq */
#define SCALE 0.08838834764831845f
#define KSTR 132                    /* Ks row stride: conflict-free LDS/STS.128 */
#define SVS  132                    /* Sv row stride: rows stay 16B-aligned */

// Flash-decode partial scratch (static device globals: allocation-free).
__device__ float g_po[(size_t)NB * KVH * Gq * Dd];   // ~7.3 MB
__device__ float g_pm[NB * KVH * Gq];
__device__ float g_pl[NB * KVH * Gq];
__device__ int   g_cnt[Bq * KVH];                    // zero-init, reset after merge

// Packed f32x2 FMA (FFMA2) — 2 MACs per issue slot; only reachable via PTX.
__device__ __forceinline__ float2 ffma2(float2 a, float2 b, float2 c) {
    unsigned long long ua = *reinterpret_cast<unsigned long long*>(&a);
    unsigned long long ub = *reinterpret_cast<unsigned long long*>(&b);
    unsigned long long uc = *reinterpret_cast<unsigned long long*>(&c);
    unsigned long long ur;
    asm("fma.rn.f32x2 %0, %1, %2, %3;" : "=l"(ur) : "l"(ua), "l"(ub), "l"(uc));
    return *reinterpret_cast<float2*>(&ur);
}

__device__ __forceinline__ void prefetch_l2(const void* p) {
    asm volatile("prefetch.global.L2 [%0];" :: "l"(p));
}

__global__ __launch_bounds__(128, 8)
void attn_fused_kernel(
    const float* __restrict__ query,
    const float* __restrict__ knew,
    const float* __restrict__ vnew,
    const float* __restrict__ kcache,
    const float* __restrict__ vcache,
    const int*   __restrict__ block_list,
    const int*   __restrict__ block_groups,
    const float* __restrict__ block_bias,
    const int*   __restrict__ block_indices,
    const int*   __restrict__ block_offsets,
    const float* __restrict__ alibi_blocks,
    const float* __restrict__ slopes,
    float*       __restrict__ out)
{
    __shared__ __align__(16) float Ks[32][KSTR];   // 16.9 KB K quarter stage (aliased later)
    __shared__ __align__(16) float Qs[Gq][Dd];     // 2 KB scaled Q
    __shared__ __align__(16) float Sv[Gq][SVS];    // 2.1 KB scores -> p -> merge coefs
    __shared__ float wmax[4][Gq];
    __shared__ float psum[4][Gq];
    __shared__ int   s_last, s_cnt;
    __shared__ short s_list[BPS + 2];

    // aliases over Ks (dead after QK; Ored consumed before flag is written)
    float (*Ored)[Gq][Dd] = reinterpret_cast<float(*)[Gq][Dd]>(&Ks[0][0]);
    unsigned char* flag   = reinterpret_cast<unsigned char*>(&Ks[0][0]) + 8192;

    // kvh-fast grid (proven R10): near-sequential aggregate DRAM stream.
    const int kvh = blockIdx.x;
    const int n   = blockIdx.y;
    const int tid = threadIdx.x;
    const int w   = tid >> 5;
    const int ln  = tid & 31;

    const int b    = block_groups[n];
    const int cblk = block_list[n];

    // validity of own token (masked tail of last block has bias = -1e9)
    const float bb_t    = block_bias[n * BS + tid];
    const float ab_t    = alibi_blocks[n * BS + tid];
    const int   valid_t = bb_t > -1.0e8f;

    // decode-token insertion: warp-uniform ballot, race-free, no smem
    int ins_slot = -1, ins_b = 0;
    {
        const unsigned mask =
            __ballot_sync(0xffffffffu, block_indices[ln] == cblk);
        if (mask) {
            ins_b    = __ffs(mask) - 1;
            ins_slot = block_offsets[ins_b];
        }
    }

    const size_t rowbase = (((size_t)cblk * BS + tid) * KVH + kvh) * Dd;
    const size_t kvrow   = (size_t)cblk * BS * KVH * Dd + (size_t)kvh * Dd;

    // stage pre-scaled Q (warp w -> head w)
    {
        const int dq = ln * 4;
        float4 q4 = *reinterpret_cast<const float4*>(
            query + (size_t)b * Hh * Dd + (size_t)(kvh * Gq + w) * Dd + dq);
        q4.x *= SCALE; q4.y *= SCALE; q4.z *= SCALE; q4.w *= SCALE;
        *reinterpret_cast<float4*>(&Qs[w][dq]) = q4;
    }
    const float sl0 = slopes[kvh * Gq + 0];
    const float sl1 = slopes[kvh * Gq + 1];
    const float sl2 = slopes[kvh * Gq + 2];
    const float sl3 = slopes[kvh * Gq + 3];

    const int nvalid = __syncthreads_count(valid_t);   // barrier + count

    // ---------------- QK: staged 32-row quarters, coalesced rows, no shfl ----------------
    // Load: warp-LDG j covers full 512B row (w*8+j) -> nL=4 (vs 32 unstaged).
    // Compute: thread = (head tid>>5, row tid&31), full 128-d dot from smem.
    {
        const int hq = w;            // head
        const int tk = ln;           // row within quarter
        float4 kb[8];                // 8 LDG.128 in flight per quarter

        auto ldg_q = [&](int q) {
            #pragma unroll
            for (int j = 0; j < 8; j++) {
                const int g = q * 32 + w * 8 + j;          // global token
                const float* src =
                    (g == ins_slot)
                      ? (knew + ((size_t)ins_b * KVH + kvh) * Dd + ln * 4)
                      : (kcache + kvrow + (size_t)g * KVH * Dd + ln * 4);
                kb[j] = *reinterpret_cast<const float4*>(src);
            }
        };

        ldg_q(0);
        #pragma unroll
        for (int q = 0; q < 4; q++) {
            const bool act = (q * 32) < nvalid;            // CTA-uniform
            if (act) {
                #pragma unroll
                for (int j = 0; j < 8; j++)
                    *reinterpret_cast<float4*>(&Ks[w * 8 + j][ln * 4]) = kb[j];
            }
            __syncthreads();                               // stage visible
            if (q < 3 && ((q + 1) * 32) < nvalid)
                ldg_q(q + 1);                              // overlap with compute
            if (act) {
                float2 a = make_float2(0.f, 0.f);
                const float* kr = &Ks[tk][0];
                #pragma unroll
                for (int c = 0; c < 32; c++) {
                    const float4 k4 = *reinterpret_cast<const float4*>(kr + c * 4);
                    const float4 q4 = *reinterpret_cast<const float4*>(&Qs[hq][c * 4]);
                    a = ffma2(make_float2(k4.x, k4.y), make_float2(q4.x, q4.y), a);
                    a = ffma2(make_float2(k4.z, k4.w), make_float2(q4.z, q4.w), a);
                }
                Sv[hq][q * 32 + tk] = a.x + a.y;
            }
            __syncthreads();                               // WAR before next STS
        }
    }

    // prefetch V tile into L2 NOW (short eviction window before PV — proven R7)
    if (valid_t) {
        const float* vr = vcache + rowbase;
        prefetch_l2(vr);       prefetch_l2(vr + 32);
        prefetch_l2(vr + 64);  prefetch_l2(vr + 96);
    }

    // ---------------- softmax (scores in Sv) ----------------
    float s0, s1, s2, s3;
    if (valid_t) {
        s0 = Sv[0][tid] + ab_t * sl0 + bb_t;
        s1 = Sv[1][tid] + ab_t * sl1 + bb_t;
        s2 = Sv[2][tid] + ab_t * sl2 + bb_t;
        s3 = Sv[3][tid] + ab_t * sl3 + bb_t;
    } else {
        s0 = s1 = s2 = s3 = -1.0e30f;
    }
    {
        float m0 = s0, m1 = s1, m2 = s2, m3 = s3;
        #pragma unroll
        for (int off = 16; off > 0; off >>= 1) {
            m0 = fmaxf(m0, __shfl_xor_sync(0xffffffffu, m0, off));
            m1 = fmaxf(m1, __shfl_xor_sync(0xffffffffu, m1, off));
            m2 = fmaxf(m2, __shfl_xor_sync(0xffffffffu, m2, off));
            m3 = fmaxf(m3, __shfl_xor_sync(0xffffffffu, m3, off));
        }
        if (ln == 0) { wmax[w][0] = m0; wmax[w][1] = m1; wmax[w][2] = m2; wmax[w][3] = m3; }
    }
    __syncthreads();
    const float m0 = fmaxf(fmaxf(wmax[0][0], wmax[1][0]), fmaxf(wmax[2][0], wmax[3][0]));
    const float m1 = fmaxf(fmaxf(wmax[0][1], wmax[1][1]), fmaxf(wmax[2][1], wmax[3][1]));
    const float m2 = fmaxf(fmaxf(wmax[0][2], wmax[1][2]), fmaxf(wmax[2][2], wmax[3][2]));
    const float m3 = fmaxf(fmaxf(wmax[0][3], wmax[1][3]), fmaxf(wmax[2][3], wmax[3][3]));

    const float p0 = valid_t ? __expf(s0 - m0) : 0.f;
    const float p1 = valid_t ? __expf(s1 - m1) : 0.f;
    const float p2 = valid_t ? __expf(s2 - m2) : 0.f;
    const float p3 = valid_t ? __expf(s3 - m3) : 0.f;
    Sv[0][tid] = p0; Sv[1][tid] = p1; Sv[2][tid] = p2; Sv[3][tid] = p3;
    {
        float t0 = p0, t1 = p1, t2 = p2, t3 = p3;
        #pragma unroll
        for (int off = 16; off > 0; off >>= 1) {
            t0 += __shfl_xor_sync(0xffffffffu, t0, off);
            t1 += __shfl_xor_sync(0xffffffffu, t1, off);
            t2 += __shfl_xor_sync(0xffffffffu, t2, off);
            t3 += __shfl_xor_sync(0xffffffffu, t3, off);
        }
        if (ln == 0) { psum[w][0] = t0; psum[w][1] = t1; psum[w][2] = t2; psum[w][3] = t3; }
    }
    __syncthreads();

    // ---------------- PV: warp w -> 32 tokens, lane owns 4 d's (R10 form) ----------------
    float2 olo[Gq], ohi[Gq];
    #pragma unroll
    for (int h = 0; h < Gq; h++) { olo[h] = make_float2(0.f, 0.f); ohi[h] = make_float2(0.f, 0.f); }
    const int d0 = ln * 4;

    if (w * 32 < nvalid) {
        const float* vbase = vcache + (((size_t)cblk * BS + w * 32) * KVH + kvh) * Dd + d0;
        #pragma unroll 2
        for (int i4 = 0; i4 < 8; i4++) {
            const int t0 = w * 32 + i4 * 4;
            float4 p4[Gq];
            #pragma unroll
            for (int h = 0; h < Gq; h++)
                p4[h] = *reinterpret_cast<const float4*>(&Sv[h][t0]);
            #pragma unroll
            for (int j = 0; j < 4; j++) {
                if (t0 + j < nvalid) {
                    const float4 v4 = *reinterpret_cast<const float4*>(
                        vbase + (size_t)(i4 * 4 + j) * KVH * Dd);
                    const float2 vlo = make_float2(v4.x, v4.y);
                    const float2 vhi = make_float2(v4.z, v4.w);
                    #pragma unroll
                    for (int h = 0; h < Gq; h++) {
                        const float pb = (j == 0) ? p4[h].x : (j == 1) ? p4[h].y
                                        : (j == 2) ? p4[h].z : p4[h].w;
                        const float2 pp = make_float2(pb, pb);
                        olo[h] = ffma2(pp, vlo, olo[h]);
                        ohi[h] = ffma2(pp, vhi, ohi[h]);
                    }
                }
            }
        }
        // exact decode-token correction: o += p_ins * (v_new - v_cache_old)
        if (ins_slot >= (w * 32) && ins_slot < (w * 32 + 32)) {
            const float4 vo = *reinterpret_cast<const float4*>(
                vcache + (((size_t)cblk * BS + ins_slot) * KVH + kvh) * Dd + d0);
            const float4 vn = *reinterpret_cast<const float4*>(
                vnew + ((size_t)ins_b * KVH + kvh) * Dd + d0);
            const float2 dlo = make_float2(vn.x - vo.x, vn.y - vo.y);
            const float2 dhi = make_float2(vn.z - vo.z, vn.w - vo.w);
            #pragma unroll
            for (int h = 0; h < Gq; h++) {
                const float pb = Sv[h][ins_slot];
                const float2 pp = make_float2(pb, pb);
                olo[h] = ffma2(pp, dlo, olo[h]);
                ohi[h] = ffma2(pp, dhi, ohi[h]);
            }
        }
    }
    __syncthreads();                 // Ks fully dead before Ored alias writes

    #pragma unroll
    for (int h = 0; h < Gq; h++)
        *reinterpret_cast<float4*>(&Ored[w][h][d0]) =
            make_float4(olo[h].x, olo[h].y, ohi[h].x, ohi[h].y);
    __syncthreads();

    // cross-warp sum + write partials (warp w -> head w, lane -> d chunk)
    {
        const float4 o0 = *reinterpret_cast<const float4*>(&Ored[0][w][d0]);
        const float4 o1 = *reinterpret_cast<const float4*>(&Ored[1][w][d0]);
        const float4 o2 = *reinterpret_cast<const float4*>(&Ored[2][w][d0]);
        const float4 o3 = *reinterpret_cast<const float4*>(&Ored[3][w][d0]);
        const float4 acc4 = make_float4(o0.x + o1.x + o2.x + o3.x,
                                        o0.y + o1.y + o2.y + o3.y,
                                        o0.z + o1.z + o2.z + o3.z,
                                        o0.w + o1.w + o2.w + o3.w);
        *reinterpret_cast<float4*>(
            &g_po[(((size_t)n * KVH + kvh) * Gq + w) * Dd + d0]) = acc4;
    }
    if (tid < Gq) {
        const size_t idx = ((size_t)n * KVH + kvh) * Gq + tid;
        g_pm[idx] = (tid == 0) ? m0 : (tid == 1) ? m1 : (tid == 2) ? m2 : m3;
        g_pl[idx] = psum[0][tid] + psum[1][tid] + psum[2][tid] + psum[3][tid];
    }

    // ---------------- fused merge: last CTA of (b, kvh) group ----------------
    __threadfence();
    __syncthreads();
    if (tid == 0)
        s_last = (atomicAdd(&g_cnt[b * KVH + kvh], 1) == (BPS - 1));
    __syncthreads();
    if (!s_last) return;

    // parallel flag fill (aliased scratch), ordered compaction
    #pragma unroll
    for (int j = 0; j < (NB + 127) / 128; j++) {
        const int nn = tid + j * 128;
        if (nn < NB) flag[nn] = (block_groups[nn] == b) ? 1 : 0;
    }
    __syncthreads();
    if (tid == 0) {
        int c = 0;
        for (int nn = 0; nn < NB && c < BPS; nn++)
            if (flag[nn]) s_list[c++] = (short)nn;
        s_cnt = c;
    }
    __syncthreads();
    const int cnt = s_cnt;

    if (tid < Gq) {                    // rescale coefs (reuse Sv rows)
        const int h = tid;
        float M = -1.0e30f;
        for (int i = 0; i < cnt; i++)
            M = fmaxf(M, g_pm[((size_t)s_list[i] * KVH + kvh) * Gq + h]);
        float den = 0.f;
        for (int i = 0; i < cnt; i++) {
            const size_t idx = ((size_t)s_list[i] * KVH + kvh) * Gq + h;
            const float e = __expf(g_pm[idx] - M);
            Sv[h][i] = e;
            den += g_pl[idx] * e;
        }
        const float inv = 1.f / den;
        for (int i = 0; i < cnt; i++) Sv[h][i] *= inv;
    }
    __syncthreads();

    {
        float4 acc4 = make_float4(0.f, 0.f, 0.f, 0.f);
        for (int i = 0; i < cnt; i++) {
            const float c = Sv[w][i];
            const float4 ov = *reinterpret_cast<const float4*>(
                &g_po[(((size_t)s_list[i] * KVH + kvh) * Gq + w) * Dd + d0]);
            acc4.x += c * ov.x; acc4.y += c * ov.y;
            acc4.z += c * ov.z; acc4.w += c * ov.w;
        }
        *reinterpret_cast<float4*>(
            &out[(size_t)b * Hh * Dd + (size_t)(kvh * Gq + w) * Dd + d0]) = acc4;
    }
    if (tid == 0) g_cnt[b * KVH + kvh] = 0;   // reset for next replay
}

extern "C" void kernel_launch(void* const* d_in, const int* in_sizes, int n_in,
                              void* d_out, int out_size)
{
    const float* query         = (const float*)d_in[0];
    const float* key           = (const float*)d_in[1];
    const float* value         = (const float*)d_in[2];
    const float* key_cache     = (const float*)d_in[3];
    const float* value_cache   = (const float*)d_in[4];
    const int*   block_list    = (const int*)d_in[5];
    const int*   block_groups  = (const int*)d_in[6];
    /* d_in[7] block_mapping: one-hot, implied by block_groups */
    const float* block_bias    = (const float*)d_in[8];
    const int*   block_indices = (const int*)d_in[9];
    const int*   block_offsets = (const int*)d_in[10];
    const float* alibi_blocks  = (const float*)d_in[11];
    const float* alibi_slopes  = (const float*)d_in[12];

    attn_fused_kernel<<<dim3(KVH, NB), 128>>>(
        query, key, value, key_cache, value_cache,
        block_list, block_groups, block_bias,
        block_indices, block_offsets, alibi_blocks, alibi_slopes,
        (float*)d_out);
}

// round 13
// speedup vs baseline: 1.3620x; 1.0167x over previous
#include <cuda_runtime.h>
#include <cstdint>

#define Bq 32
#define Hh 32
#define KVH 8
#define Gq 4
#define Dd 128
#define BS 128
#define NB 448
#define BPS 14                      /* blocks per sequence = NB/Bq */
#define SCALE 0.08838834764831845f
#define KSTR 132                    /* Ks row stride: conflict-free LDS/STS.128 */
#define SVS  132                    /* Sv row stride: rows stay 16B-aligned */

// Flash-decode partial scratch (static device globals: allocation-free).
__device__ float g_po[(size_t)NB * KVH * Gq * Dd];   // ~7.3 MB
__device__ float g_pm[NB * KVH * Gq];
__device__ float g_pl[NB * KVH * Gq];
__device__ int   g_cnt[Bq * KVH];                    // zero-init, reset after merge

// Packed f32x2 FMA (FFMA2) — 2 MACs per issue slot; only reachable via PTX.
__device__ __forceinline__ float2 ffma2(float2 a, float2 b, float2 c) {
    unsigned long long ua = *reinterpret_cast<unsigned long long*>(&a);
    unsigned long long ub = *reinterpret_cast<unsigned long long*>(&b);
    unsigned long long uc = *reinterpret_cast<unsigned long long*>(&c);
    unsigned long long ur;
    asm("fma.rn.f32x2 %0, %1, %2, %3;" : "=l"(ur) : "l"(ua), "l"(ub), "l"(uc));
    return *reinterpret_cast<float2*>(&ur);
}

__device__ __forceinline__ void prefetch_l2(const void* p) {
    asm volatile("prefetch.global.L2 [%0];" :: "l"(p));
}

__global__ __launch_bounds__(128, 8)
void attn_fused_kernel(
    const float* __restrict__ query,
    const float* __restrict__ knew,
    const float* __restrict__ vnew,
    const float* __restrict__ kcache,
    const float* __restrict__ vcache,
    const int*   __restrict__ block_list,
    const int*   __restrict__ block_groups,
    const float* __restrict__ block_bias,
    const int*   __restrict__ block_indices,
    const int*   __restrict__ block_offsets,
    const float* __restrict__ alibi_blocks,
    const float* __restrict__ slopes,
    float*       __restrict__ out)
{
    __shared__ __align__(16) float Ks[32][KSTR];   // 16.9 KB K quarter stage (aliased later)
    __shared__ __align__(16) float Qs[Gq][Dd];     // 2 KB scaled Q
    __shared__ __align__(16) float Sv[Gq][SVS];    // 2.1 KB scores -> p -> merge coefs
    __shared__ float wmax[4][Gq];
    __shared__ float psum[4][Gq];
    __shared__ int   s_last, s_cnt;
    __shared__ short s_list[BPS + 2];

    // aliases over Ks (dead after QK; Ored consumed before flag is written)
    float (*Ored)[Gq][Dd] = reinterpret_cast<float(*)[Gq][Dd]>(&Ks[0][0]);
    unsigned char* flag   = reinterpret_cast<unsigned char*>(&Ks[0][0]) + 8192;

    // kvh-fast grid (proven R10): near-sequential aggregate DRAM stream.
    const int kvh = blockIdx.x;
    const int n   = blockIdx.y;
    const int tid = threadIdx.x;
    const int w   = tid >> 5;
    const int ln  = tid & 31;

    const int b    = block_groups[n];
    const int cblk = block_list[n];

    // validity of own token (masked tail of last block has bias = -1e9)
    const float bb_t    = block_bias[n * BS + tid];
    const float ab_t    = alibi_blocks[n * BS + tid];
    const int   valid_t = bb_t > -1.0e8f;

    // decode-token insertion: warp-uniform ballot, race-free, no smem
    int ins_slot = -1, ins_b = 0;
    {
        const unsigned mask =
            __ballot_sync(0xffffffffu, block_indices[ln] == cblk);
        if (mask) {
            ins_b    = __ffs(mask) - 1;
            ins_slot = block_offsets[ins_b];
        }
    }

    const size_t rowbase = (((size_t)cblk * BS + tid) * KVH + kvh) * Dd;
    const size_t kvrow   = (size_t)cblk * BS * KVH * Dd + (size_t)kvh * Dd;

    // stage pre-scaled Q (warp w -> head w)
    {
        const int dq = ln * 4;
        float4 q4 = *reinterpret_cast<const float4*>(
            query + (size_t)b * Hh * Dd + (size_t)(kvh * Gq + w) * Dd + dq);
        q4.x *= SCALE; q4.y *= SCALE; q4.z *= SCALE; q4.w *= SCALE;
        *reinterpret_cast<float4*>(&Qs[w][dq]) = q4;
    }
    const float sl0 = slopes[kvh * Gq + 0];
    const float sl1 = slopes[kvh * Gq + 1];
    const float sl2 = slopes[kvh * Gq + 2];
    const float sl3 = slopes[kvh * Gq + 3];

    const int nvalid = __syncthreads_count(valid_t);   // barrier + count

    // ---------------- QK: staged 32-row quarters, 8-lane row split ----------------
    // Load: warp-LDG j covers full 512B row (w*8+j) -> nL=4.
    // Compute: thread = (row w*8+(ln&7), chunk ln>>3); each Ks chunk read ONCE,
    // used for all 4 heads (Qs phase-broadcast); chunk sums via shfl xor 8,16.
    {
        const int rloc = w * 8 + (ln & 7);   // row within quarter
        const int ch   = ln >> 3;            // 32-float chunk (0..3)
        float4 kb[8];                        // 8 LDG.128 in flight per quarter

        auto ldg_q = [&](int q) {
            #pragma unroll
            for (int j = 0; j < 8; j++) {
                const int g = q * 32 + w * 8 + j;          // global token
                const float* src =
                    (g == ins_slot)
                      ? (knew + ((size_t)ins_b * KVH + kvh) * Dd + ln * 4)
                      : (kcache + kvrow + (size_t)g * KVH * Dd + ln * 4);
                kb[j] = *reinterpret_cast<const float4*>(src);
            }
        };

        ldg_q(0);
        #pragma unroll
        for (int q = 0; q < 4; q++) {
            const bool act = (q * 32) < nvalid;            // CTA-uniform
            if (act) {
                #pragma unroll
                for (int j = 0; j < 8; j++)
                    *reinterpret_cast<float4*>(&Ks[w * 8 + j][ln * 4]) = kb[j];
            }
            __syncthreads();                               // stage visible
            if (q < 3 && ((q + 1) * 32) < nvalid)
                ldg_q(q + 1);                              // overlap with compute
            if (act) {
                float2 a0 = make_float2(0.f, 0.f), a1 = a0, a2 = a0, a3 = a0;
                #pragma unroll
                for (int i = 0; i < 8; i++) {
                    const int f4 = ch + 4 * i;             // interleaved float4 idx
                    const float4 k4 = *reinterpret_cast<const float4*>(&Ks[rloc][f4 * 4]);
                    const float2 klo = make_float2(k4.x, k4.y);
                    const float2 khi = make_float2(k4.z, k4.w);
                    const float4 q0 = *reinterpret_cast<const float4*>(&Qs[0][f4 * 4]);
                    const float4 q1 = *reinterpret_cast<const float4*>(&Qs[1][f4 * 4]);
                    const float4 q2 = *reinterpret_cast<const float4*>(&Qs[2][f4 * 4]);
                    const float4 q3 = *reinterpret_cast<const float4*>(&Qs[3][f4 * 4]);
                    a0 = ffma2(klo, make_float2(q0.x, q0.y), a0);
                    a0 = ffma2(khi, make_float2(q0.z, q0.w), a0);
                    a1 = ffma2(klo, make_float2(q1.x, q1.y), a1);
                    a1 = ffma2(khi, make_float2(q1.z, q1.w), a1);
                    a2 = ffma2(klo, make_float2(q2.x, q2.y), a2);
                    a2 = ffma2(khi, make_float2(q2.z, q2.w), a2);
                    a3 = ffma2(klo, make_float2(q3.x, q3.y), a3);
                    a3 = ffma2(khi, make_float2(q3.z, q3.w), a3);
                }
                float t0 = a0.x + a0.y, t1 = a1.x + a1.y;
                float t2 = a2.x + a2.y, t3 = a3.x + a3.y;
                t0 += __shfl_xor_sync(0xffffffffu, t0, 8);
                t1 += __shfl_xor_sync(0xffffffffu, t1, 8);
                t2 += __shfl_xor_sync(0xffffffffu, t2, 8);
                t3 += __shfl_xor_sync(0xffffffffu, t3, 8);
                t0 += __shfl_xor_sync(0xffffffffu, t0, 16);
                t1 += __shfl_xor_sync(0xffffffffu, t1, 16);
                t2 += __shfl_xor_sync(0xffffffffu, t2, 16);
                t3 += __shfl_xor_sync(0xffffffffu, t3, 16);
                if (ln < 8) {
                    const int tok = q * 32 + rloc;
                    Sv[0][tok] = t0; Sv[1][tok] = t1;
                    Sv[2][tok] = t2; Sv[3][tok] = t3;
                }
            }
            __syncthreads();                               // WAR before next STS
        }
    }

    // prefetch V tile into L2 NOW (short eviction window before PV — proven R7)
    if (valid_t) {
        const float* vr = vcache + rowbase;
        prefetch_l2(vr);       prefetch_l2(vr + 32);
        prefetch_l2(vr + 64);  prefetch_l2(vr + 96);
    }

    // ---------------- softmax (scores in Sv) ----------------
    float s0, s1, s2, s3;
    if (valid_t) {
        s0 = Sv[0][tid] + ab_t * sl0 + bb_t;
        s1 = Sv[1][tid] + ab_t * sl1 + bb_t;
        s2 = Sv[2][tid] + ab_t * sl2 + bb_t;
        s3 = Sv[3][tid] + ab_t * sl3 + bb_t;
    } else {
        s0 = s1 = s2 = s3 = -1.0e30f;
    }
    {
        float m0 = s0, m1 = s1, m2 = s2, m3 = s3;
        #pragma unroll
        for (int off = 16; off > 0; off >>= 1) {
            m0 = fmaxf(m0, __shfl_xor_sync(0xffffffffu, m0, off));
            m1 = fmaxf(m1, __shfl_xor_sync(0xffffffffu, m1, off));
            m2 = fmaxf(m2, __shfl_xor_sync(0xffffffffu, m2, off));
            m3 = fmaxf(m3, __shfl_xor_sync(0xffffffffu, m3, off));
        }
        if (ln == 0) { wmax[w][0] = m0; wmax[w][1] = m1; wmax[w][2] = m2; wmax[w][3] = m3; }
    }
    __syncthreads();
    const float m0 = fmaxf(fmaxf(wmax[0][0], wmax[1][0]), fmaxf(wmax[2][0], wmax[3][0]));
    const float m1 = fmaxf(fmaxf(wmax[0][1], wmax[1][1]), fmaxf(wmax[2][1], wmax[3][1]));
    const float m2 = fmaxf(fmaxf(wmax[0][2], wmax[1][2]), fmaxf(wmax[2][2], wmax[3][2]));
    const float m3 = fmaxf(fmaxf(wmax[0][3], wmax[1][3]), fmaxf(wmax[2][3], wmax[3][3]));

    const float p0 = valid_t ? __expf(s0 - m0) : 0.f;
    const float p1 = valid_t ? __expf(s1 - m1) : 0.f;
    const float p2 = valid_t ? __expf(s2 - m2) : 0.f;
    const float p3 = valid_t ? __expf(s3 - m3) : 0.f;
    Sv[0][tid] = p0; Sv[1][tid] = p1; Sv[2][tid] = p2; Sv[3][tid] = p3;
    {
        float t0 = p0, t1 = p1, t2 = p2, t3 = p3;
        #pragma unroll
        for (int off = 16; off > 0; off >>= 1) {
            t0 += __shfl_xor_sync(0xffffffffu, t0, off);
            t1 += __shfl_xor_sync(0xffffffffu, t1, off);
            t2 += __shfl_xor_sync(0xffffffffu, t2, off);
            t3 += __shfl_xor_sync(0xffffffffu, t3, off);
        }
        if (ln == 0) { psum[w][0] = t0; psum[w][1] = t1; psum[w][2] = t2; psum[w][3] = t3; }
    }
    __syncthreads();

    // ---------------- PV: warp w -> 32 tokens, lane owns 4 d's (R10 form) ----------------
    float2 olo[Gq], ohi[Gq];
    #pragma unroll
    for (int h = 0; h < Gq; h++) { olo[h] = make_float2(0.f, 0.f); ohi[h] = make_float2(0.f, 0.f); }
    const int d0 = ln * 4;

    if (w * 32 < nvalid) {
        const float* vbase = vcache + (((size_t)cblk * BS + w * 32) * KVH + kvh) * Dd + d0;
        #pragma unroll 2
        for (int i4 = 0; i4 < 8; i4++) {
            const int t0 = w * 32 + i4 * 4;
            float4 p4[Gq];
            #pragma unroll
            for (int h = 0; h < Gq; h++)
                p4[h] = *reinterpret_cast<const float4*>(&Sv[h][t0]);
            #pragma unroll
            for (int j = 0; j < 4; j++) {
                if (t0 + j < nvalid) {
                    const float4 v4 = *reinterpret_cast<const float4*>(
                        vbase + (size_t)(i4 * 4 + j) * KVH * Dd);
                    const float2 vlo = make_float2(v4.x, v4.y);
                    const float2 vhi = make_float2(v4.z, v4.w);
                    #pragma unroll
                    for (int h = 0; h < Gq; h++) {
                        const float pb = (j == 0) ? p4[h].x : (j == 1) ? p4[h].y
                                        : (j == 2) ? p4[h].z : p4[h].w;
                        const float2 pp = make_float2(pb, pb);
                        olo[h] = ffma2(pp, vlo, olo[h]);
                        ohi[h] = ffma2(pp, vhi, ohi[h]);
                    }
                }
            }
        }
        // exact decode-token correction: o += p_ins * (v_new - v_cache_old)
        if (ins_slot >= (w * 32) && ins_slot < (w * 32 + 32)) {
            const float4 vo = *reinterpret_cast<const float4*>(
                vcache + (((size_t)cblk * BS + ins_slot) * KVH + kvh) * Dd + d0);
            const float4 vn = *reinterpret_cast<const float4*>(
                vnew + ((size_t)ins_b * KVH + kvh) * Dd + d0);
            const float2 dlo = make_float2(vn.x - vo.x, vn.y - vo.y);
            const float2 dhi = make_float2(vn.z - vo.z, vn.w - vo.w);
            #pragma unroll
            for (int h = 0; h < Gq; h++) {
                const float pb = Sv[h][ins_slot];
                const float2 pp = make_float2(pb, pb);
                olo[h] = ffma2(pp, dlo, olo[h]);
                ohi[h] = ffma2(pp, dhi, ohi[h]);
            }
        }
    }
    __syncthreads();                 // Ks fully dead before Ored alias writes

    #pragma unroll
    for (int h = 0; h < Gq; h++)
        *reinterpret_cast<float4*>(&Ored[w][h][d0]) =
            make_float4(olo[h].x, olo[h].y, ohi[h].x, ohi[h].y);
    __syncthreads();

    // cross-warp sum + write partials (warp w -> head w, lane -> d chunk)
    {
        const float4 o0 = *reinterpret_cast<const float4*>(&Ored[0][w][d0]);
        const float4 o1 = *reinterpret_cast<const float4*>(&Ored[1][w][d0]);
        const float4 o2 = *reinterpret_cast<const float4*>(&Ored[2][w][d0]);
        const float4 o3 = *reinterpret_cast<const float4*>(&Ored[3][w][d0]);
        const float4 acc4 = make_float4(o0.x + o1.x + o2.x + o3.x,
                                        o0.y + o1.y + o2.y + o3.y,
                                        o0.z + o1.z + o2.z + o3.z,
                                        o0.w + o1.w + o2.w + o3.w);
        *reinterpret_cast<float4*>(
            &g_po[(((size_t)n * KVH + kvh) * Gq + w) * Dd + d0]) = acc4;
    }
    if (tid < Gq) {
        const size_t idx = ((size_t)n * KVH + kvh) * Gq + tid;
        g_pm[idx] = (tid == 0) ? m0 : (tid == 1) ? m1 : (tid == 2) ? m2 : m3;
        g_pl[idx] = psum[0][tid] + psum[1][tid] + psum[2][tid] + psum[3][tid];
    }

    // ---------------- fused merge: last CTA of (b, kvh) group ----------------
    __threadfence();
    __syncthreads();
    if (tid == 0)
        s_last = (atomicAdd(&g_cnt[b * KVH + kvh], 1) == (BPS - 1));
    __syncthreads();
    if (!s_last) return;

    // parallel flag fill (aliased scratch), ordered compaction
    #pragma unroll
    for (int j = 0; j < (NB + 127) / 128; j++) {
        const int nn = tid + j * 128;
        if (nn < NB) flag[nn] = (block_groups[nn] == b) ? 1 : 0;
    }
    __syncthreads();
    if (tid == 0) {
        int c = 0;
        for (int nn = 0; nn < NB && c < BPS; nn++)
            if (flag[nn]) s_list[c++] = (short)nn;
        s_cnt = c;
    }
    __syncthreads();
    const int cnt = s_cnt;

    if (tid < Gq) {                    // rescale coefs (reuse Sv rows)
        const int h = tid;
        float M = -1.0e30f;
        for (int i = 0; i < cnt; i++)
            M = fmaxf(M, g_pm[((size_t)s_list[i] * KVH + kvh) * Gq + h]);
        float den = 0.f;
        for (int i = 0; i < cnt; i++) {
            const size_t idx = ((size_t)s_list[i] * KVH + kvh) * Gq + h;
            const float e = __expf(g_pm[idx] - M);
            Sv[h][i] = e;
            den += g_pl[idx] * e;
        }
        const float inv = 1.f / den;
        for (int i = 0; i < cnt; i++) Sv[h][i] *= inv;
    }
    __syncthreads();

    {
        float4 acc4 = make_float4(0.f, 0.f, 0.f, 0.f);
        for (int i = 0; i < cnt; i++) {
            const float c = Sv[w][i];
            const float4 ov = *reinterpret_cast<const float4*>(
                &g_po[(((size_t)s_list[i] * KVH + kvh) * Gq + w) * Dd + d0]);
            acc4.x += c * ov.x; acc4.y += c * ov.y;
            acc4.z += c * ov.z; acc4.w += c * ov.w;
        }
        *reinterpret_cast<float4*>(
            &out[(size_t)b * Hh * Dd + (size_t)(kvh * Gq + w) * Dd + d0]) = acc4;
    }
    if (tid == 0) g_cnt[b * KVH + kvh] = 0;   // reset for next replay
}

extern "C" void kernel_launch(void* const* d_in, const int* in_sizes, int n_in,
                              void* d_out, int out_size)
{
    const float* query         = (const float*)d_in[0];
    const float* key           = (const float*)d_in[1];
    const float* value         = (const float*)d_in[2];
    const float* key_cache     = (const float*)d_in[3];
    const float* value_cache   = (const float*)d_in[4];
    const int*   block_list    = (const int*)d_in[5];
    const int*   block_groups  = (const int*)d_in[6];
    /* d_in[7] block_mapping: one-hot, implied by block_groups */
    const float* block_bias    = (const float*)d_in[8];
    const int*   block_indices = (const int*)d_in[9];
    const int*   block_offsets = (const int*)d_in[10];
    const float* alibi_blocks  = (const float*)d_in[11];
    const float* alibi_slopes  = (const float*)d_in[12];

    attn_fused_kernel<<<dim3(KVH, NB), 128>>>(
        query, key, value, key_cache, value_cache,
        block_list, block_groups, block_bias,
        block_indices, block_offsets, alibi_blocks, alibi_slopes,
        (float*)d_out);
}

// round 14
// speedup vs baseline: 1.3691x; 1.0052x over previous
#include <cuda_runtime.h>
#include <cstdint>

#define Bq 32
#define Hh 32
#define KVH 8
#define Gq 4
#define Dd 128
#define BS 128
#define NB 448
#define BPS 14                      /* blocks per sequence = NB/Bq */
#define SCALE 0.08838834764831845f
#define KSTR 132                    /* Ks row stride: conflict-free LDS/STS.128 */
#define SVS  132                    /* Sv row stride: rows stay 16B-aligned */

// Flash-decode partial scratch (static device globals: allocation-free).
__device__ float g_po[(size_t)NB * KVH * Gq * Dd];   // ~7.3 MB
__device__ float g_pm[NB * KVH * Gq];
__device__ float g_pl[NB * KVH * Gq];
__device__ int   g_cnt[Bq * KVH];                    // zero-init, reset after merge

// Packed f32x2 FMA (FFMA2) — 2 MACs per issue slot; only reachable via PTX.
__device__ __forceinline__ float2 ffma2(float2 a, float2 b, float2 c) {
    unsigned long long ua = *reinterpret_cast<unsigned long long*>(&a);
    unsigned long long ub = *reinterpret_cast<unsigned long long*>(&b);
    unsigned long long uc = *reinterpret_cast<unsigned long long*>(&c);
    unsigned long long ur;
    asm("fma.rn.f32x2 %0, %1, %2, %3;" : "=l"(ur) : "l"(ua), "l"(ub), "l"(uc));
    return *reinterpret_cast<float2*>(&ur);
}

__device__ __forceinline__ void prefetch_l2(const void* p) {
    asm volatile("prefetch.global.L2 [%0];" :: "l"(p));
}

__global__ __launch_bounds__(128, 8)
void attn_fused_kernel(
    const float* __restrict__ query,
    const float* __restrict__ knew,
    const float* __restrict__ vnew,
    const float* __restrict__ kcache,
    const float* __restrict__ vcache,
    const int*   __restrict__ block_list,
    const int*   __restrict__ block_groups,
    const float* __restrict__ block_bias,
    const int*   __restrict__ block_indices,
    const int*   __restrict__ block_offsets,
    const float* __restrict__ alibi_blocks,
    const float* __restrict__ slopes,
    float*       __restrict__ out)
{
    __shared__ __align__(16) float Ks[32][KSTR];   // 16.9 KB K quarter stage (aliased later)
    __shared__ __align__(16) float Qs[Gq][Dd];     // 2 KB scaled Q
    __shared__ __align__(16) float Sv[Gq][SVS];    // 2.1 KB scores -> p -> merge coefs
    __shared__ float wmax[4][Gq];
    __shared__ float psum[4][Gq];
    __shared__ int   s_last, s_cnt;
    __shared__ short s_list[BPS + 2];

    // aliases over Ks (dead after QK; Ored consumed before flag is written)
    float (*Ored)[Gq][Dd] = reinterpret_cast<float(*)[Gq][Dd]>(&Ks[0][0]);
    unsigned char* flag   = reinterpret_cast<unsigned char*>(&Ks[0][0]) + 8192;

    // kvh-fast grid (proven R10): near-sequential aggregate DRAM stream.
    const int kvh = blockIdx.x;
    const int n   = blockIdx.y;
    const int tid = threadIdx.x;
    const int w   = tid >> 5;
    const int ln  = tid & 31;

    const int b    = block_groups[n];
    const int cblk = block_list[n];

    // validity of own token (masked tail of last block has bias = -1e9)
    const float bb_t    = block_bias[n * BS + tid];
    const float ab_t    = alibi_blocks[n * BS + tid];
    const int   valid_t = bb_t > -1.0e8f;

    // decode-token insertion: warp-uniform ballot, race-free, no smem
    int ins_slot = -1, ins_b = 0;
    {
        const unsigned mask =
            __ballot_sync(0xffffffffu, block_indices[ln] == cblk);
        if (mask) {
            ins_b    = __ffs(mask) - 1;
            ins_slot = block_offsets[ins_b];
        }
    }

    const size_t rowbase = (((size_t)cblk * BS + tid) * KVH + kvh) * Dd;
    const size_t kvrow   = (size_t)cblk * BS * KVH * Dd + (size_t)kvh * Dd;

    // stage pre-scaled Q (warp w -> head w)
    {
        const int dq = ln * 4;
        float4 q4 = *reinterpret_cast<const float4*>(
            query + (size_t)b * Hh * Dd + (size_t)(kvh * Gq + w) * Dd + dq);
        q4.x *= SCALE; q4.y *= SCALE; q4.z *= SCALE; q4.w *= SCALE;
        *reinterpret_cast<float4*>(&Qs[w][dq]) = q4;
    }
    const float sl0 = slopes[kvh * Gq + 0];
    const float sl1 = slopes[kvh * Gq + 1];
    const float sl2 = slopes[kvh * Gq + 2];
    const float sl3 = slopes[kvh * Gq + 3];

    const int nvalid = __syncthreads_count(valid_t);   // barrier + count (Qs visible)

    // ---------------- QK: staged quarters, WARP-PRIVATE rows (no CTA barriers) ----------------
    // Warp w stores rows w*8+j and computes ONLY those rows -> all stage/WAR
    // sync is intra-warp (__syncwarp); warps free-run, LDGs stay in flight.
    {
        const int rloc = w * 8 + (ln & 7);   // row within quarter (own warp's rows)
        const int ch   = ln >> 3;            // 32-float chunk (0..3)
        float4 kb[8];                        // 8 LDG.128 in flight per quarter

        auto ldg_q = [&](int q) {
            #pragma unroll
            for (int j = 0; j < 8; j++) {
                const int g = q * 32 + w * 8 + j;          // global token
                const float* src =
                    (g == ins_slot)
                      ? (knew + ((size_t)ins_b * KVH + kvh) * Dd + ln * 4)
                      : (kcache + kvrow + (size_t)g * KVH * Dd + ln * 4);
                kb[j] = *reinterpret_cast<const float4*>(src);
            }
        };

        ldg_q(0);
        #pragma unroll
        for (int q = 0; q < 4; q++) {
            const bool act = (q * 32) < nvalid;            // CTA-uniform
            if (act) {
                #pragma unroll
                for (int j = 0; j < 8; j++)
                    *reinterpret_cast<float4*>(&Ks[w * 8 + j][ln * 4]) = kb[j];
            }
            __syncwarp();                                  // own stores visible to warp
            if (q < 3 && ((q + 1) * 32) < nvalid)
                ldg_q(q + 1);                              // overlap with compute
            if (act) {
                float2 a0 = make_float2(0.f, 0.f), a1 = a0, a2 = a0, a3 = a0;
                #pragma unroll
                for (int i = 0; i < 8; i++) {
                    const int f4 = ch + 4 * i;             // interleaved float4 idx
                    const float4 k4 = *reinterpret_cast<const float4*>(&Ks[rloc][f4 * 4]);
                    const float2 klo = make_float2(k4.x, k4.y);
                    const float2 khi = make_float2(k4.z, k4.w);
                    const float4 q0 = *reinterpret_cast<const float4*>(&Qs[0][f4 * 4]);
                    const float4 q1 = *reinterpret_cast<const float4*>(&Qs[1][f4 * 4]);
                    const float4 q2 = *reinterpret_cast<const float4*>(&Qs[2][f4 * 4]);
                    const float4 q3 = *reinterpret_cast<const float4*>(&Qs[3][f4 * 4]);
                    a0 = ffma2(klo, make_float2(q0.x, q0.y), a0);
                    a0 = ffma2(khi, make_float2(q0.z, q0.w), a0);
                    a1 = ffma2(klo, make_float2(q1.x, q1.y), a1);
                    a1 = ffma2(khi, make_float2(q1.z, q1.w), a1);
                    a2 = ffma2(klo, make_float2(q2.x, q2.y), a2);
                    a2 = ffma2(khi, make_float2(q2.z, q2.w), a2);
                    a3 = ffma2(klo, make_float2(q3.x, q3.y), a3);
                    a3 = ffma2(khi, make_float2(q3.z, q3.w), a3);
                }
                float t0 = a0.x + a0.y, t1 = a1.x + a1.y;
                float t2 = a2.x + a2.y, t3 = a3.x + a3.y;
                t0 += __shfl_xor_sync(0xffffffffu, t0, 8);
                t1 += __shfl_xor_sync(0xffffffffu, t1, 8);
                t2 += __shfl_xor_sync(0xffffffffu, t2, 8);
                t3 += __shfl_xor_sync(0xffffffffu, t3, 8);
                t0 += __shfl_xor_sync(0xffffffffu, t0, 16);
                t1 += __shfl_xor_sync(0xffffffffu, t1, 16);
                t2 += __shfl_xor_sync(0xffffffffu, t2, 16);
                t3 += __shfl_xor_sync(0xffffffffu, t3, 16);
                if (ln < 8) {
                    const int tok = q * 32 + rloc;
                    Sv[0][tok] = t0; Sv[1][tok] = t1;
                    Sv[2][tok] = t2; Sv[3][tok] = t3;
                }
            }
            __syncwarp();                                  // WAR before next STS (own rows)
        }
    }

    // prefetch V tile into L2 NOW (short eviction window before PV — proven R7)
    if (valid_t) {
        const float* vr = vcache + rowbase;
        prefetch_l2(vr);       prefetch_l2(vr + 32);
        prefetch_l2(vr + 64);  prefetch_l2(vr + 96);
    }
    __syncthreads();             // cross-warp Sv visibility for softmax

    // ---------------- softmax (scores in Sv) ----------------
    float s0, s1, s2, s3;
    if (valid_t) {
        s0 = Sv[0][tid] + ab_t * sl0 + bb_t;
        s1 = Sv[1][tid] + ab_t * sl1 + bb_t;
        s2 = Sv[2][tid] + ab_t * sl2 + bb_t;
        s3 = Sv[3][tid] + ab_t * sl3 + bb_t;
    } else {
        s0 = s1 = s2 = s3 = -1.0e30f;
    }
    {
        float m0 = s0, m1 = s1, m2 = s2, m3 = s3;
        #pragma unroll
        for (int off = 16; off > 0; off >>= 1) {
            m0 = fmaxf(m0, __shfl_xor_sync(0xffffffffu, m0, off));
            m1 = fmaxf(m1, __shfl_xor_sync(0xffffffffu, m1, off));
            m2 = fmaxf(m2, __shfl_xor_sync(0xffffffffu, m2, off));
            m3 = fmaxf(m3, __shfl_xor_sync(0xffffffffu, m3, off));
        }
        if (ln == 0) { wmax[w][0] = m0; wmax[w][1] = m1; wmax[w][2] = m2; wmax[w][3] = m3; }
    }
    __syncthreads();
    const float m0 = fmaxf(fmaxf(wmax[0][0], wmax[1][0]), fmaxf(wmax[2][0], wmax[3][0]));
    const float m1 = fmaxf(fmaxf(wmax[0][1], wmax[1][1]), fmaxf(wmax[2][1], wmax[3][1]));
    const float m2 = fmaxf(fmaxf(wmax[0][2], wmax[1][2]), fmaxf(wmax[2][2], wmax[3][2]));
    const float m3 = fmaxf(fmaxf(wmax[0][3], wmax[1][3]), fmaxf(wmax[2][3], wmax[3][3]));

    const float p0 = valid_t ? __expf(s0 - m0) : 0.f;
    const float p1 = valid_t ? __expf(s1 - m1) : 0.f;
    const float p2 = valid_t ? __expf(s2 - m2) : 0.f;
    const float p3 = valid_t ? __expf(s3 - m3) : 0.f;
    Sv[0][tid] = p0; Sv[1][tid] = p1; Sv[2][tid] = p2; Sv[3][tid] = p3;
    {
        float t0 = p0, t1 = p1, t2 = p2, t3 = p3;
        #pragma unroll
        for (int off = 16; off > 0; off >>= 1) {
            t0 += __shfl_xor_sync(0xffffffffu, t0, off);
            t1 += __shfl_xor_sync(0xffffffffu, t1, off);
            t2 += __shfl_xor_sync(0xffffffffu, t2, off);
            t3 += __shfl_xor_sync(0xffffffffu, t3, off);
        }
        if (ln == 0) { psum[w][0] = t0; psum[w][1] = t1; psum[w][2] = t2; psum[w][3] = t3; }
    }
    __syncthreads();

    // ---------------- PV: warp w -> 32 tokens, lane owns 4 d's (R10 form) ----------------
    float2 olo[Gq], ohi[Gq];
    #pragma unroll
    for (int h = 0; h < Gq; h++) { olo[h] = make_float2(0.f, 0.f); ohi[h] = make_float2(0.f, 0.f); }
    const int d0 = ln * 4;

    if (w * 32 < nvalid) {
        const float* vbase = vcache + (((size_t)cblk * BS + w * 32) * KVH + kvh) * Dd + d0;
        #pragma unroll 2
        for (int i4 = 0; i4 < 8; i4++) {
            const int t0 = w * 32 + i4 * 4;
            float4 p4[Gq];
            #pragma unroll
            for (int h = 0; h < Gq; h++)
                p4[h] = *reinterpret_cast<const float4*>(&Sv[h][t0]);
            #pragma unroll
            for (int j = 0; j < 4; j++) {
                if (t0 + j < nvalid) {
                    const float4 v4 = *reinterpret_cast<const float4*>(
                        vbase + (size_t)(i4 * 4 + j) * KVH * Dd);
                    const float2 vlo = make_float2(v4.x, v4.y);
                    const float2 vhi = make_float2(v4.z, v4.w);
                    #pragma unroll
                    for (int h = 0; h < Gq; h++) {
                        const float pb = (j == 0) ? p4[h].x : (j == 1) ? p4[h].y
                                        : (j == 2) ? p4[h].z : p4[h].w;
                        const float2 pp = make_float2(pb, pb);
                        olo[h] = ffma2(pp, vlo, olo[h]);
                        ohi[h] = ffma2(pp, vhi, ohi[h]);
                    }
                }
            }
        }
        // exact decode-token correction: o += p_ins * (v_new - v_cache_old)
        if (ins_slot >= (w * 32) && ins_slot < (w * 32 + 32)) {
            const float4 vo = *reinterpret_cast<const float4*>(
                vcache + (((size_t)cblk * BS + ins_slot) * KVH + kvh) * Dd + d0);
            const float4 vn = *reinterpret_cast<const float4*>(
                vnew + ((size_t)ins_b * KVH + kvh) * Dd + d0);
            const float2 dlo = make_float2(vn.x - vo.x, vn.y - vo.y);
            const float2 dhi = make_float2(vn.z - vo.z, vn.w - vo.w);
            #pragma unroll
            for (int h = 0; h < Gq; h++) {
                const float pb = Sv[h][ins_slot];
                const float2 pp = make_float2(pb, pb);
                olo[h] = ffma2(pp, dlo, olo[h]);
                ohi[h] = ffma2(pp, dhi, ohi[h]);
            }
        }
    }
    __syncthreads();                 // Ks fully dead before Ored alias writes

    #pragma unroll
    for (int h = 0; h < Gq; h++)
        *reinterpret_cast<float4*>(&Ored[w][h][d0]) =
            make_float4(olo[h].x, olo[h].y, ohi[h].x, ohi[h].y);
    __syncthreads();

    // cross-warp sum + write partials (warp w -> head w, lane -> d chunk)
    {
        const float4 o0 = *reinterpret_cast<const float4*>(&Ored[0][w][d0]);
        const float4 o1 = *reinterpret_cast<const float4*>(&Ored[1][w][d0]);
        const float4 o2 = *reinterpret_cast<const float4*>(&Ored[2][w][d0]);
        const float4 o3 = *reinterpret_cast<const float4*>(&Ored[3][w][d0]);
        const float4 acc4 = make_float4(o0.x + o1.x + o2.x + o3.x,
                                        o0.y + o1.y + o2.y + o3.y,
                                        o0.z + o1.z + o2.z + o3.z,
                                        o0.w + o1.w + o2.w + o3.w);
        *reinterpret_cast<float4*>(
            &g_po[(((size_t)n * KVH + kvh) * Gq + w) * Dd + d0]) = acc4;
    }
    if (tid < Gq) {
        const size_t idx = ((size_t)n * KVH + kvh) * Gq + tid;
        g_pm[idx] = (tid == 0) ? m0 : (tid == 1) ? m1 : (tid == 2) ? m2 : m3;
        g_pl[idx] = psum[0][tid] + psum[1][tid] + psum[2][tid] + psum[3][tid];
    }

    // ---------------- fused merge: last CTA of (b, kvh) group ----------------
    __threadfence();
    __syncthreads();
    if (tid == 0)
        s_last = (atomicAdd(&g_cnt[b * KVH + kvh], 1) == (BPS - 1));
    __syncthreads();
    if (!s_last) return;

    // parallel flag fill (aliased scratch), ordered compaction
    #pragma unroll
    for (int j = 0; j < (NB + 127) / 128; j++) {
        const int nn = tid + j * 128;
        if (nn < NB) flag[nn] = (block_groups[nn] == b) ? 1 : 0;
    }
    __syncthreads();
    if (tid == 0) {
        int c = 0;
        for (int nn = 0; nn < NB && c < BPS; nn++)
            if (flag[nn]) s_list[c++] = (short)nn;
        s_cnt = c;
    }
    __syncthreads();
    const int cnt = s_cnt;

    if (tid < Gq) {                    // rescale coefs (reuse Sv rows)
        const int h = tid;
        float M = -1.0e30f;
        for (int i = 0; i < cnt; i++)
            M = fmaxf(M, g_pm[((size_t)s_list[i] * KVH + kvh) * Gq + h]);
        float den = 0.f;
        for (int i = 0; i < cnt; i++) {
            const size_t idx = ((size_t)s_list[i] * KVH + kvh) * Gq + h;
            const float e = __expf(g_pm[idx] - M);
            Sv[h][i] = e;
            den += g_pl[idx] * e;
        }
        const float inv = 1.f / den;
        for (int i = 0; i < cnt; i++) Sv[h][i] *= inv;
    }
    __syncthreads();

    {
        float4 acc4 = make_float4(0.f, 0.f, 0.f, 0.f);
        for (int i = 0; i < cnt; i++) {
            const float c = Sv[w][i];
            const float4 ov = *reinterpret_cast<const float4*>(
                &g_po[(((size_t)s_list[i] * KVH + kvh) * Gq + w) * Dd + d0]);
            acc4.x += c * ov.x; acc4.y += c * ov.y;
            acc4.z += c * ov.z; acc4.w += c * ov.w;
        }
        *reinterpret_cast<float4*>(
            &out[(size_t)b * Hh * Dd + (size_t)(kvh * Gq + w) * Dd + d0]) = acc4;
    }
    if (tid == 0) g_cnt[b * KVH + kvh] = 0;   // reset for next replay
}

extern "C" void kernel_launch(void* const* d_in, const int* in_sizes, int n_in,
                              void* d_out, int out_size)
{
    const float* query         = (const float*)d_in[0];
    const float* key           = (const float*)d_in[1];
    const float* value         = (const float*)d_in[2];
    const float* key_cache     = (const float*)d_in[3];
    const float* value_cache   = (const float*)d_in[4];
    const int*   block_list    = (const int*)d_in[5];
    const int*   block_groups  = (const int*)d_in[6];
    /* d_in[7] block_mapping: one-hot, implied by block_groups */
    const float* block_bias    = (const float*)d_in[8];
    const int*   block_indices = (const int*)d_in[9];
    const int*   block_offsets = (const int*)d_in[10];
    const float* alibi_blocks  = (const float*)d_in[11];
    const float* alibi_slopes  = (const float*)d_in[12];

    attn_fused_kernel<<<dim3(KVH, NB), 128>>>(
        query, key, value, key_cache, value_cache,
        block_list, block_groups, block_bias,
        block_indices, block_offsets, alibi_blocks, alibi_slopes,
        (float*)d_out);
}